// round 16
// baseline (speedup 1.0000x reference)
#include <cuda_runtime.h>
#include <stdint.h>

// Problem dims (fixed by the reference)
#define D_ 8
#define B_ 16
#define E_ 2048
#define O_ 2048

#define CAP  2048           // per-batch triple capacity (mean ~328, max ~420)
#define ZCH  16             // list chunks per batch
#define TPB  128            // phase2 threads per block
#define OV   4              // o-columns per thread (float4)

// Compacted per-batch triple lists. Entry = {dm_off, coef}.
// dm_off = (d*E + e)*O;  w_off = dm_off & (E*O - 1) = dm_off & 0x3FFFFF.
__device__ __align__(8) uint2 g_list[B_ * CAP];   // 256 KB
__device__ int g_cnt[B_];

// ---------------------------------------------------------------------------
// Phase 1 (single pass): one thread per (d,e). Counts actives in SMEM,
// reserves contiguous ranges with one global atomic per (block, b),
// writes 8-byte entries.
// ---------------------------------------------------------------------------
__global__ __launch_bounds__(128)
void phase1_kernel(const float* __restrict__ Xd,
                   const float* __restrict__ Wshort,
                   const int*   __restrict__ signs_pre) {
    __shared__ int s_cnt[B_], s_base[B_], s_pos[B_];

    const int t = blockIdx.x * 128 + threadIdx.x;   // [0, 16384)
    const int d = t >> 11;
    const int e = t & (E_ - 1);

    if (threadIdx.x < B_) s_cnt[threadIdx.x] = 0;
    __syncthreads();

    const float s = (float)(2 * signs_pre[e] - 1);  // {0,1} -> {-1,+1}

    unsigned m = 0u;
    float c[B_];
#pragma unroll
    for (int b = 0; b < B_; ++b) {
        int idx = (d * B_ + b) * E_ + e;            // coalesced over e per b
        float x  = Xd[idx];                         // exactly 0.0 or 1.0
        c[b] = s * (1.0f + Wshort[idx]);
        if (x != 0.0f) {
            m |= (1u << b);
            atomicAdd(&s_cnt[b], 1);
        }
    }
    __syncthreads();

    if (threadIdx.x < B_) {
        s_base[threadIdx.x] = atomicAdd(&g_cnt[threadIdx.x], s_cnt[threadIdx.x]);
        s_pos[threadIdx.x]  = 0;
    }
    __syncthreads();

    if (m == 0u) return;

    const unsigned dm_off = (unsigned)((d * E_ + e) * O_);
#pragma unroll
    for (int b = 0; b < B_; ++b) {
        if ((m >> b) & 1u) {
            int pos = s_base[b] + atomicAdd(&s_pos[b], 1);
            if (pos < CAP)
                g_list[b * CAP + pos] = make_uint2(dm_off, __float_as_uint(c[b]));
        }
    }
}

// ---------------------------------------------------------------------------
// Phase 2: sparse stream, float4 columns, 5-stage software pipeline:
//   iter i issues:  W[i+4]  and  (w[i+2] != 0) ? dmap[i+2]
//   iter i consumes: triple i  (its W landed at i-4, its dmap at i-2)
// Steady-state MLP per thread ~5 (3 W + 2 dmap in flight).
// Entry layout: .x = dm_off (w_off = .x & 0x3FFFFF), .y = coef bits.
// ---------------------------------------------------------------------------
__device__ __forceinline__ bool nz4(const float4 v) {
    return (__float_as_uint(v.x) | __float_as_uint(v.y) |
            __float_as_uint(v.z) | __float_as_uint(v.w)) != 0u;
}

__device__ __forceinline__ void fma4(float4& acc, const float4 w,
                                     const float cf, const float4 dm) {
    acc.x = fmaf(w.x * cf, dm.x, acc.x);
    acc.y = fmaf(w.y * cf, dm.y, acc.y);
    acc.z = fmaf(w.z * cf, dm.z, acc.z);
    acc.w = fmaf(w.w * cf, dm.w, acc.w);
}

__global__ __launch_bounds__(TPB, 6)
void phase2_kernel(const float* __restrict__ W,
                   const float* __restrict__ dmap,
                   float*       __restrict__ out) {
    __shared__ __align__(8) uint2 s_ent[CAP / ZCH + 2];   // up to 128 entries

    const int o = (blockIdx.x * TPB + threadIdx.x) * OV;  // 16B-aligned column
    const int b = blockIdx.y;
    const int z = blockIdx.z;

    int cnt = g_cnt[b];
    if (cnt > CAP) cnt = CAP;
    const int c0 = (cnt * z) / ZCH;
    const int c1 = (cnt * (z + 1)) / ZCH;
    const int n  = c1 - c0;
    if (n <= 0) return;

    {
        const uint2* src = &g_list[b * CAP + c0];
        for (int i = threadIdx.x; i < n; i += TPB)
            s_ent[i] = src[i];
    }
    __syncthreads();

    const float4 z4 = make_float4(0.0f, 0.0f, 0.0f, 0.0f);
    float4 acc = z4;

    if (n >= 5) {
        // prolog: W for triples 0..3, dmap for 0..1
        uint2  t0 = s_ent[0], t1 = s_ent[1], t2 = s_ent[2], t3 = s_ent[3];
        float4 w0 = __ldg((const float4*)&W[(t0.x & 0x3FFFFFu) + o]);
        float4 w1 = __ldg((const float4*)&W[(t1.x & 0x3FFFFFu) + o]);
        float4 w2 = __ldg((const float4*)&W[(t2.x & 0x3FFFFFu) + o]);
        float4 w3 = __ldg((const float4*)&W[(t3.x & 0x3FFFFFu) + o]);
        float4 d0 = z4, d1 = z4;
        if (nz4(w0)) d0 = __ldg((const float4*)&dmap[t0.x + o]);
        if (nz4(w1)) d1 = __ldg((const float4*)&dmap[t1.x + o]);

        int i = 0;
        for (; i < n - 4; ++i) {
            const uint2  t4 = s_ent[i + 4];
            const float4 w4 = __ldg((const float4*)&W[(t4.x & 0x3FFFFFu) + o]);
            float4 d2 = z4;
            if (nz4(w2)) d2 = __ldg((const float4*)&dmap[t2.x + o]);

            fma4(acc, w0, __uint_as_float(t0.y), d0);

            t0 = t1; w0 = w1; d0 = d1;
            t1 = t2; w1 = w2; d1 = d2;
            t2 = t3; w2 = w3;
            t3 = t4; w3 = w4;
        }
        // epilog: 4 remaining triples (w0..w3 resident, d0,d1 resident)
        float4 d2 = z4, d3 = z4;
        if (nz4(w2)) d2 = __ldg((const float4*)&dmap[t2.x + o]);
        if (nz4(w3)) d3 = __ldg((const float4*)&dmap[t3.x + o]);
        fma4(acc, w0, __uint_as_float(t0.y), d0);
        fma4(acc, w1, __uint_as_float(t1.y), d1);
        fma4(acc, w2, __uint_as_float(t2.y), d2);
        fma4(acc, w3, __uint_as_float(t3.y), d3);
    } else {
        // short chunk: simple loop
        for (int i = 0; i < n; ++i) {
            const uint2  t = s_ent[i];
            const float4 w = __ldg((const float4*)&W[(t.x & 0x3FFFFFu) + o]);
            float4 dm = z4;
            if (nz4(w)) dm = __ldg((const float4*)&dmap[t.x + o]);
            fma4(acc, w, __uint_as_float(t.y), dm);
        }
    }

    // Guarded cross-chunk reduction
    float* dst = &out[b * O_ + o];
    if (acc.x != 0.0f) atomicAdd(dst + 0, acc.x);
    if (acc.y != 0.0f) atomicAdd(dst + 1, acc.y);
    if (acc.z != 0.0f) atomicAdd(dst + 2, acc.z);
    if (acc.w != 0.0f) atomicAdd(dst + 3, acc.w);
}

// ---------------------------------------------------------------------------
// Launch: memset out + counters -> phase1 -> phase2. Graph-capturable.
// Input order per metadata: W, Xd, delaymap, Wshort, signs_pre.
// ---------------------------------------------------------------------------
extern "C" void kernel_launch(void* const* d_in, const int* in_sizes, int n_in,
                              void* d_out, int out_size) {
    const float* W      = (const float*)d_in[0];  // (E, O)
    const float* Xd     = (const float*)d_in[1];  // (D, B, E)
    const float* dmap   = (const float*)d_in[2];  // (D, E, O)
    const float* Wshort = (const float*)d_in[3];  // (D, B, E)
    const int*   signs  = (const int*)  d_in[4];  // (E,)
    float* out = (float*)d_out;                   // (B, O)

    cudaMemsetAsync(out, 0, (size_t)out_size * sizeof(float), 0);

    void* cnt_ptr = nullptr;
    cudaGetSymbolAddress(&cnt_ptr, g_cnt);        // host-side query, capture-safe
    cudaMemsetAsync(cnt_ptr, 0, sizeof(int) * B_, 0);

    phase1_kernel<<<D_ * E_ / 128, 128>>>(Xd, Wshort, signs);

    dim3 grid(O_ / (TPB * OV), B_, ZCH);          // 4 x 16 x 16 = 1024 blocks
    phase2_kernel<<<grid, TPB>>>(W, dmap, out);
}

// round 17
// speedup vs baseline: 1.0748x; 1.0748x over previous
#include <cuda_runtime.h>
#include <stdint.h>

// Problem dims (fixed by the reference)
#define D_ 8
#define B_ 16
#define E_ 2048
#define O_ 2048

#define P1B  128            // phase1 blocks; each owns 128 consecutive (d,e)
#define SEG  32             // entry slots per (batch, phase1-block); mean fill 2.6
#define ZCH  32             // phase2 chunks per batch
#define SPB  (P1B / ZCH)    // 4 segments per chunk
#define TPB  128            // phase2 threads per block
#define OV   4              // o-columns per thread (float4)

// Direct-indexed segment lists: no global atomics, no counter memset.
// Entry = {dm_off, coef};  dm_off = (d*E+e)*O;  w_off = dm_off & 0x3FFFFF.
__device__ __align__(16) uint2 g_list[B_][P1B][SEG];   // 512 KB
__device__ int g_segcnt[B_ * P1B];                      // 8 KB, fully overwritten

// ---------------------------------------------------------------------------
// Phase 1: one thread per (d,e). Each block owns a private SEG-slot segment
// per batch (smem cursor only). Also zeroes `out` (replaces a memset node).
// Writes ALL g_segcnt entries unconditionally -> no prior zeroing needed.
// ---------------------------------------------------------------------------
__global__ __launch_bounds__(128)
void phase1_kernel(const float* __restrict__ Xd,
                   const float* __restrict__ Wshort,
                   const int*   __restrict__ signs_pre,
                   float*       __restrict__ out) {
    __shared__ int s_pos[B_];

    const int tid = threadIdx.x;
    const int bid = blockIdx.x;
    const int t   = bid * 128 + tid;                // [0, 16384)

    // zero the output: 32768 floats / 16384 threads = one float2 each
    reinterpret_cast<float2*>(out)[t] = make_float2(0.0f, 0.0f);

    if (tid < B_) s_pos[tid] = 0;
    __syncthreads();

    const int d = t >> 11;
    const int e = t & (E_ - 1);
    const float s = (float)(2 * signs_pre[e] - 1);  // {0,1} -> {-1,+1}
    const unsigned dm_off = (unsigned)((d * E_ + e) * O_);

#pragma unroll
    for (int b = 0; b < B_; ++b) {
        const int idx = (d * B_ + b) * E_ + e;      // coalesced over e
        const float x = Xd[idx];                    // exactly 0.0 or 1.0
        if (x != 0.0f) {
            const float c = s * (1.0f + Wshort[idx]);
            const int pos = atomicAdd(&s_pos[b], 1);   // smem, ~2.6 mean
            if (pos < SEG)
                g_list[b][bid][pos] = make_uint2(dm_off, __float_as_uint(c));
        }
    }
    __syncthreads();

    if (tid < B_) {
        int c = s_pos[tid];
        g_segcnt[tid * P1B + bid] = (c < SEG) ? c : SEG;
    }
}

// ---------------------------------------------------------------------------
// Phase 2: sparse stream, float4 columns, software pipeline:
//   iter i issues  W[i+4]  and  (w[i+2] != 0) ? dmap[i+2]
//   iter i consumes triple i (W landed at i-4, dmap at i-2).
// Entry indices re-read from SMEM at use sites (saves ~12 regs vs rotation).
// ---------------------------------------------------------------------------
__device__ __forceinline__ bool nz4(const float4 v) {
    return (__float_as_uint(v.x) | __float_as_uint(v.y) |
            __float_as_uint(v.z) | __float_as_uint(v.w)) != 0u;
}

__device__ __forceinline__ void fma4(float4& acc, const float4 w,
                                     const float cf, const float4 dm) {
    acc.x = fmaf(w.x * cf, dm.x, acc.x);
    acc.y = fmaf(w.y * cf, dm.y, acc.y);
    acc.z = fmaf(w.z * cf, dm.z, acc.z);
    acc.w = fmaf(w.w * cf, dm.w, acc.w);
}

__global__ __launch_bounds__(TPB, 8)
void phase2_kernel(const float* __restrict__ W,
                   const float* __restrict__ dmap,
                   float*       __restrict__ out) {
    __shared__ __align__(8) uint2 s_ent[SPB * SEG];   // 128 entries max
    __shared__ int s_cnt[SPB];

    const int o = (blockIdx.x * TPB + threadIdx.x) * OV;  // 16B-aligned column
    const int b = blockIdx.y;
    const int seg0 = blockIdx.z * SPB;

    if (threadIdx.x < SPB)
        s_cnt[threadIdx.x] = g_segcnt[b * P1B + seg0 + threadIdx.x];
    __syncthreads();

    int off[SPB + 1];
    off[0] = 0;
#pragma unroll
    for (int j = 0; j < SPB; ++j) off[j + 1] = off[j] + s_cnt[j];
    const int n = off[SPB];
    if (n == 0) return;

    // compact the 4 segments into contiguous SMEM (SPB*SEG == TPB threads)
    {
        const int j = threadIdx.x / SEG;
        const int k = threadIdx.x % SEG;
        if (k < s_cnt[j])
            s_ent[off[j] + k] = g_list[b][seg0 + j][k];
    }
    __syncthreads();

    const float4 z4 = make_float4(0.0f, 0.0f, 0.0f, 0.0f);
    float4 acc = z4;

    if (n >= 5) {
        float4 w0 = __ldg((const float4*)&W[(s_ent[0].x & 0x3FFFFFu) + o]);
        float4 w1 = __ldg((const float4*)&W[(s_ent[1].x & 0x3FFFFFu) + o]);
        float4 w2 = __ldg((const float4*)&W[(s_ent[2].x & 0x3FFFFFu) + o]);
        float4 w3 = __ldg((const float4*)&W[(s_ent[3].x & 0x3FFFFFu) + o]);
        float4 d0 = z4, d1 = z4;
        if (nz4(w0)) d0 = __ldg((const float4*)&dmap[s_ent[0].x + o]);
        if (nz4(w1)) d1 = __ldg((const float4*)&dmap[s_ent[1].x + o]);

        int i = 0;
        for (; i < n - 4; ++i) {
            const float4 w4 =
                __ldg((const float4*)&W[(s_ent[i + 4].x & 0x3FFFFFu) + o]);
            float4 d2 = z4;
            if (nz4(w2)) d2 = __ldg((const float4*)&dmap[s_ent[i + 2].x + o]);

            fma4(acc, w0, __uint_as_float(s_ent[i].y), d0);

            w0 = w1; d0 = d1;
            w1 = w2; d1 = d2;
            w2 = w3;
            w3 = w4;
        }
        // epilog: triples i..i+3 (= n-4..n-1); w0..w3 resident, d0,d1 resident
        float4 d2 = z4, d3 = z4;
        if (nz4(w2)) d2 = __ldg((const float4*)&dmap[s_ent[i + 2].x + o]);
        if (nz4(w3)) d3 = __ldg((const float4*)&dmap[s_ent[i + 3].x + o]);
        fma4(acc, w0, __uint_as_float(s_ent[i].y),     d0);
        fma4(acc, w1, __uint_as_float(s_ent[i + 1].y), d1);
        fma4(acc, w2, __uint_as_float(s_ent[i + 2].y), d2);
        fma4(acc, w3, __uint_as_float(s_ent[i + 3].y), d3);
    } else {
        for (int i = 0; i < n; ++i) {
            const uint2  t = s_ent[i];
            const float4 w = __ldg((const float4*)&W[(t.x & 0x3FFFFFu) + o]);
            float4 dm = z4;
            if (nz4(w)) dm = __ldg((const float4*)&dmap[t.x + o]);
            fma4(acc, w, __uint_as_float(t.y), dm);
        }
    }

    // Guarded cross-chunk reduction
    float* dst = &out[b * O_ + o];
    if (acc.x != 0.0f) atomicAdd(dst + 0, acc.x);
    if (acc.y != 0.0f) atomicAdd(dst + 1, acc.y);
    if (acc.z != 0.0f) atomicAdd(dst + 2, acc.z);
    if (acc.w != 0.0f) atomicAdd(dst + 3, acc.w);
}

// ---------------------------------------------------------------------------
// Launch: ONLY two kernel nodes (out-zeroing folded into phase1; no counter
// memsets needed — g_segcnt fully overwritten each call). Graph-capturable.
// Input order per metadata: W, Xd, delaymap, Wshort, signs_pre.
// ---------------------------------------------------------------------------
extern "C" void kernel_launch(void* const* d_in, const int* in_sizes, int n_in,
                              void* d_out, int out_size) {
    const float* W      = (const float*)d_in[0];  // (E, O)
    const float* Xd     = (const float*)d_in[1];  // (D, B, E)
    const float* dmap   = (const float*)d_in[2];  // (D, E, O)
    const float* Wshort = (const float*)d_in[3];  // (D, B, E)
    const int*   signs  = (const int*)  d_in[4];  // (E,)
    float* out = (float*)d_out;                   // (B, O)

    phase1_kernel<<<P1B, 128>>>(Xd, Wshort, signs, out);

    dim3 grid(O_ / (TPB * OV), B_, ZCH);          // 4 x 16 x 32 = 2048 blocks
    phase2_kernel<<<grid, TPB>>>(W, dmap, out);
}